// round 15
// baseline (speedup 1.0000x reference)
#include <cuda_runtime.h>
#include <math.h>
#include <stdint.h>

#define N_NODES 25600
#define N_EDGES 204800
#define ETOT    (N_EDGES + N_NODES)   // 230400
#define EHALF   (ETOT/2)              // 115200
#define IN_CH   6
#define HID     64
#define HEADS   4
#define C1      (HEADS*HID)           // 256
#define G_GRAPHS 512
#define T_STEPS  50
#define OUT_DIM  30
#define NEG_SLOPE 0.2f
#define BN_INV 0.9999950000374996f    // 1/sqrt(1+1e-5)

// ---------------- scratch ----------------
__device__ __align__(16) float g_x8[N_NODES*8];
__device__ __align__(16) float g_asrc1[N_NODES*4];
__device__ __align__(16) float g_adst1[N_NODES*4];
__device__ __align__(16) float g_xagg[N_NODES*32];    // 4 heads x [x0..x5, denom, 0]
__device__ __align__(16) float g_hproj2[N_NODES*HID];
__device__ float g_asrc2[N_NODES];
__device__ float g_adst2[N_NODES];
__device__ float g_denom2[N_NODES];
__device__ __align__(16) float g_accum2[N_NODES*HID];
__device__ __align__(16) float g_xgates[N_NODES*C1];  // (t, g, 256)
__device__ __align__(16) uint32_t g_W2t[256*64];      // tf32 bits, [k][j]
__device__ __align__(16) uint32_t g_WihT[64*256];     // tf32 bits, [k][j] (Wih^T)

// ---------------- helpers ----------------
__device__ __forceinline__ float lrelu(float v) { return v > 0.f ? v : NEG_SLOPE*v; }
__device__ __forceinline__ float eluf(float v)  { return v > 0.f ? v : (__expf(v) - 1.f); }
__device__ __forceinline__ float sigf(float v)  { return 1.f/(1.f+expf(-v)); }

__device__ __forceinline__ void redAdd4(float* addr, float a, float b, float c, float d) {
    asm volatile("red.global.add.v4.f32 [%0], {%1,%2,%3,%4};"
                 :: "l"(addr), "f"(a), "f"(b), "f"(c), "f"(d) : "memory");
}
__device__ __forceinline__ void ffma2(unsigned long long& d, unsigned long long a,
                                      unsigned long long b) {
    asm("fma.rn.f32x2 %0, %1, %2, %0;" : "+l"(d) : "l"(a), "l"(b));
}
__device__ __forceinline__ unsigned long long pk(float a, float b) {
    unsigned long long r;
    asm("mov.b64 %0, {%1, %2};" : "=l"(r) : "f"(a), "f"(b));
    return r;
}
__device__ __forceinline__ float2 unpk(unsigned long long v) {
    float2 r;
    asm("mov.b64 {%0, %1}, %2;" : "=f"(r.x), "=f"(r.y) : "l"(v));
    return r;
}
__device__ __forceinline__ uint32_t f2tf32(float v) {
    uint32_t r;
    asm("cvt.rna.tf32.f32 %0, %1;" : "=r"(r) : "f"(v));
    return r;
}
// m16n8k8 tf32 MMA, fp32 accumulate (in-place)
__device__ __forceinline__ void mma_tf32(float* d, const uint32_t* a, const uint32_t* b) {
    asm("mma.sync.aligned.m16n8k8.row.col.f32.tf32.tf32.f32 "
        "{%0,%1,%2,%3},{%4,%5,%6,%7},{%8,%9},{%0,%1,%2,%3};"
        : "+f"(d[0]), "+f"(d[1]), "+f"(d[2]), "+f"(d[3])
        : "r"(a[0]), "r"(a[1]), "r"(a[2]), "r"(a[3]), "r"(b[0]), "r"(b[1]));
}

// ---------------- kernels ----------------
// merged prep: wsrc/wdst in smem (per-block redundant), weight conversion, att1 dots.
// grid exactly 100 x 256 = 25600 threads.
__global__ void k_prep2(const float* __restrict__ W1, const float* __restrict__ as1,
                        const float* __restrict__ ad1,
                        const float* __restrict__ W2, const float* __restrict__ Wih,
                        const float* __restrict__ x) {
    __shared__ float swsrc[24], swdst[24];
    int t = threadIdx.x;
    int i = blockIdx.x*256 + t;

    if (i < 16384) {
        g_W2t[i] = f2tf32(W2[i]);                  // layout already [k][64]
        int j = i >> 6, k = i & 63;                // Wih is [j][k]
        g_WihT[k*256 + j] = f2tf32(Wih[i]);        // -> [k][256]
    }
    if (t < 24) {
        int k = t >> 2, h = t & 3;
        float s = 0.f;
        for (int c = 0; c < 64; c++) s += W1[k*C1 + h*64 + c] * as1[h*64 + c];
        swsrc[t] = s;
    } else if (t >= 32 && t < 56) {
        int q = t - 32, k = q >> 2, h = q & 3;
        float s = 0.f;
        for (int c = 0; c < 64; c++) s += W1[k*C1 + h*64 + c] * ad1[h*64 + c];
        swdst[q] = s;
    }
    __syncthreads();

    int n = i;
    float2 xa = *(const float2*)&x[n*6];
    float2 xb = *(const float2*)&x[n*6 + 2];
    float2 xc = *(const float2*)&x[n*6 + 4];
    float xv[6] = {xa.x, xa.y, xb.x, xb.y, xc.x, xc.y};
    float s[4] = {0,0,0,0}, d[4] = {0,0,0,0};
    #pragma unroll
    for (int k = 0; k < 6; k++) {
        #pragma unroll
        for (int h = 0; h < 4; h++) {
            s[h] += xv[k]*swsrc[k*4+h];
            d[h] += xv[k]*swdst[k*4+h];
        }
    }
    *(float4*)&g_asrc1[n*4] = make_float4(s[0],s[1],s[2],s[3]);
    *(float4*)&g_adst1[n*4] = make_float4(d[0],d[1],d[2],d[3]);
    *(float4*)&g_x8[n*8]     = make_float4(xv[0],xv[1],xv[2],xv[3]);
    *(float4*)&g_x8[n*8 + 4] = make_float4(xv[4],xv[5],0.f,0.f);
}

// 2 edges per thread for doubled memory-level parallelism
__global__ void k_esum1(const int* __restrict__ ei) {
    int e0 = blockIdx.x*blockDim.x + threadIdx.x;
    if (e0 >= EHALF) return;
    #pragma unroll
    for (int rep = 0; rep < 2; rep++) {
        int e = e0 + rep*EHALF;
        int s, d;
        if (e < N_EDGES) { s = ei[e]; d = ei[N_EDGES + e]; } else { s = d = e - N_EDGES; }
        float4 as = *(const float4*)&g_asrc1[s*4];
        float4 ad = *(const float4*)&g_adst1[d*4];
        float ex[4];
        ex[0] = expf(lrelu(as.x + ad.x));
        ex[1] = expf(lrelu(as.y + ad.y));
        ex[2] = expf(lrelu(as.z + ad.z));
        ex[3] = expf(lrelu(as.w + ad.w));
        float4 xa = *(const float4*)&g_x8[s*8];
        float4 xb = *(const float4*)&g_x8[s*8 + 4];
        float* base = &g_xagg[d*32];
        #pragma unroll
        for (int h = 0; h < 4; h++) {
            float w = ex[h];
            redAdd4(base + h*8,     w*xa.x, w*xa.y, w*xa.z, w*xa.w);
            redAdd4(base + h*8 + 4, w*xb.x, w*xb.y, w,      0.f);
        }
    }
}

// fused GAT2 projection via tf32 MMA. 32 nodes/block, 4 CTAs/SM,
// fully unrolled K loop (immediate offsets), B frags from L1.
#define P2N 32
#define H1STR 260          // (4r + k) % 32 -> conflict-free A frags
__global__ void __launch_bounds__(256, 4) k_proj2f(
        const float* __restrict__ W1, const float* __restrict__ b1,
        const float* __restrict__ g1, const float* __restrict__ be1,
        const float* __restrict__ as2, const float* __restrict__ ad2) {
    extern __shared__ float sm[];
    float* sW1p = sm;                      // [256][8]: {w0..w5, A, C} f32 = 2048
    float* h1s  = sW1p + 2048;             // [32][260] tf32 bits
    float* sAs  = h1s + P2N*H1STR;         // 64
    float* sAd  = sAs + 64;                // 64
    float* sS   = sAd + 64;                // 128
    float* sD   = sS + 128;                // 128
    int t = threadIdx.x;
    int nbase = blockIdx.x * P2N;

    for (int i = t; i < 2048; i += 256) {
        int c = i >> 3, r = i & 7;
        float v;
        if (r < 6)       v = W1[r*C1 + c];
        else if (r == 6) v = g1[c]*BN_INV;
        else { float A = g1[c]*BN_INV; v = A*b1[c] + be1[c]; }
        sW1p[i] = v;
    }
    if (t < 64)            sAs[t] = as2[t];
    else if (t < 128)      sAd[t-64] = ad2[t-64];
    __syncthreads();

    // phase 1: thread (nl, q) computes h1 cols [q*32, q*32+32) of node nl (head q>>1)
    {
        int nl = t & 31, q = t >> 5;
        int n  = nbase + nl;
        int h  = q >> 1;
        float4 v0 = *(const float4*)&g_xagg[n*32 + h*8];
        float4 v1 = *(const float4*)&g_xagg[n*32 + h*8 + 4];
        float inv = 1.f / v1.z;
        float x0 = v0.x*inv, x1 = v0.y*inv, x2 = v0.z*inv;
        float x3 = v0.w*inv, x4 = v1.x*inv, x5 = v1.y*inv;
        #pragma unroll 8
        for (int c2 = 0; c2 < 32; c2++) {
            int c = q*32 + c2;
            float4 wa = *(const float4*)&sW1p[c*8];
            float4 wb = *(const float4*)&sW1p[c*8 + 4];
            float dot = x0*wa.x + x1*wa.y + x2*wa.z + x3*wa.w + x4*wb.x + x5*wb.y;
            h1s[nl*H1STR + c] = __uint_as_float(f2tf32(eluf(dot*wb.z + wb.w)));
        }
    }
    __syncthreads();

    // phase 2: MMA. warp w: mt=w&1 (16 nodes), nq=w>>1 (16 cols = 2 n-tiles)
    const uint32_t* h1u = (const uint32_t*)h1s;
    int w = t >> 5, l = t & 31;
    int g = l >> 2, c = l & 3;
    int mt = w & 1, nq = w >> 1;
    int r0 = mt*16 + g;

    float acc[2][4];
    #pragma unroll
    for (int nt = 0; nt < 2; nt++) { acc[nt][0]=0; acc[nt][1]=0; acc[nt][2]=0; acc[nt][3]=0; }

    const uint32_t* ap = h1u + r0*H1STR + c;
    const uint32_t* wp = &g_W2t[c*64 + nq*16 + g];
    #pragma unroll
    for (int ks = 0; ks < 32; ks++) {
        const int kb = ks*8;
        uint32_t a[4];
        a[0] = ap[kb];
        a[1] = ap[kb + 8*H1STR];
        a[2] = ap[kb + 4];
        a[3] = ap[kb + 8*H1STR + 4];
        #pragma unroll
        for (int nt = 0; nt < 2; nt++) {
            uint32_t b[2];
            b[0] = __ldg(&wp[kb*64 + nt*8]);
            b[1] = __ldg(&wp[(kb + 4)*64 + nt*8]);
            mma_tf32(acc[nt], a, b);
        }
    }

    // epilogue: store hproj2 + att2 partial dots
    float s0 = 0.f, d0 = 0.f, s1 = 0.f, d1 = 0.f;
    int n0 = nbase + r0, n1 = n0 + 8;
    #pragma unroll
    for (int nt = 0; nt < 2; nt++) {
        int col = nq*16 + nt*8 + 2*c;
        *(float2*)&g_hproj2[n0*64 + col] = make_float2(acc[nt][0], acc[nt][1]);
        *(float2*)&g_hproj2[n1*64 + col] = make_float2(acc[nt][2], acc[nt][3]);
        s0 += acc[nt][0]*sAs[col] + acc[nt][1]*sAs[col+1];
        d0 += acc[nt][0]*sAd[col] + acc[nt][1]*sAd[col+1];
        s1 += acc[nt][2]*sAs[col] + acc[nt][3]*sAs[col+1];
        d1 += acc[nt][2]*sAd[col] + acc[nt][3]*sAd[col+1];
    }
    #pragma unroll
    for (int m = 1; m < 4; m <<= 1) {
        s0 += __shfl_xor_sync(~0u, s0, m);
        d0 += __shfl_xor_sync(~0u, d0, m);
        s1 += __shfl_xor_sync(~0u, s1, m);
        d1 += __shfl_xor_sync(~0u, d1, m);
    }
    if (c == 0) {
        sS[r0*4 + nq] = s0;     sD[r0*4 + nq] = d0;
        sS[(r0+8)*4 + nq] = s1; sD[(r0+8)*4 + nq] = d1;
    }
    __syncthreads();
    if (t < P2N) {
        float ss = sS[t*4] + sS[t*4+1] + sS[t*4+2] + sS[t*4+3];
        float dd = sD[t*4] + sD[t*4+1] + sD[t*4+2] + sD[t*4+3];
        g_asrc2[nbase + t] = ss;
        g_adst2[nbase + t] = dd;
    }
}

// 8 threads/edge, 2 edges per thread: denom += ex; accum2[dst] += ex*hproj2[src]
__global__ void k_esum2(const int* __restrict__ ei) {
    int gt = blockIdx.x*blockDim.x + threadIdx.x;
    int e0 = gt >> 3, q = gt & 7;
    if (e0 >= EHALF) return;
    #pragma unroll
    for (int rep = 0; rep < 2; rep++) {
        int e = e0 + rep*EHALF;
        int s, d;
        if (e < N_EDGES) { s = ei[e]; d = ei[N_EDGES + e]; } else { s = d = e - N_EDGES; }
        float ex = expf(lrelu(g_asrc2[s] + g_adst2[d]));
        if (q == 0) atomicAdd(&g_denom2[d], ex);
        int c = q*8;
        float4 v1 = *(const float4*)&g_hproj2[s*64 + c];
        float4 v2 = *(const float4*)&g_hproj2[s*64 + c + 4];
        redAdd4(&g_accum2[d*64 + c],     v1.x*ex, v1.y*ex, v1.z*ex, v1.w*ex);
        redAdd4(&g_accum2[d*64 + c + 4], v2.x*ex, v2.y*ex, v2.z*ex, v2.w*ex);
    }
}

// fused: h2 staged once as tf32; xgates = h2@Wih^T + biases via tf32 MMA (scattered rows).
#define XGN 32
#define H2STR 68           // (4r + k) % 32 -> conflict-free A frags
__global__ void __launch_bounds__(256, 4) k_xgates2(
        const float* __restrict__ bih, const float* __restrict__ bhh,
        const float* __restrict__ b2, const float* __restrict__ g2,
        const float* __restrict__ be2,
        const int* __restrict__ batch, const int* __restrict__ ntime) {
    extern __shared__ float sm[];
    float* h2s   = sm;                    // [32][68] tf32 bits
    float* sBias = h2s + XGN*H2STR;       // 256
    float* sA2   = sBias + 256;           // 64
    float* sC2   = sA2 + 64;              // 64
    float* sInv  = sC2 + 64;              // 32
    int t = threadIdx.x;
    int nbase = blockIdx.x * XGN;

    sBias[t] = bih[t] + bhh[t];
    if (t < 64) {
        float A = g2[t]*BN_INV;
        sA2[t] = A;
        sC2[t] = A*b2[t] + be2[t];
    } else if (t >= 128 && t < 160) {
        sInv[t-128] = 1.f / g_denom2[nbase + (t-128)];
    }
    __syncthreads();

    for (int i = t; i < XGN*64; i += 256) {
        int nn = i >> 6, k = i & 63;
        float v = g_accum2[(nbase + nn)*64 + k] * sInv[nn];
        h2s[nn*H2STR + k] = __uint_as_float(f2tf32(eluf(v*sA2[k] + sC2[k])));
    }
    __syncthreads();

    const uint32_t* h2u = (const uint32_t*)h2s;
    int w = t >> 5, l = t & 31;
    int g = l >> 2, c = l & 3;
    int mt = w & 1, nh = w >> 1;   // nh in 0..3: 64-col group
    int r0 = mt*16 + g;

    float acc[8][4];
    #pragma unroll
    for (int nt = 0; nt < 8; nt++) { acc[nt][0]=0; acc[nt][1]=0; acc[nt][2]=0; acc[nt][3]=0; }

    const uint32_t* ap = h2u + r0*H2STR + c;
    const uint32_t* wp = &g_WihT[c*256 + nh*64 + g];
    #pragma unroll
    for (int ks = 0; ks < 8; ks++) {
        const int kb = ks*8;
        uint32_t a[4];
        a[0] = ap[kb];
        a[1] = ap[kb + 8*H2STR];
        a[2] = ap[kb + 4];
        a[3] = ap[kb + 8*H2STR + 4];
        #pragma unroll
        for (int nt = 0; nt < 8; nt++) {
            uint32_t b[2];
            b[0] = __ldg(&wp[kb*256 + nt*8]);
            b[1] = __ldg(&wp[(kb + 4)*256 + nt*8]);
            mma_tf32(acc[nt], a, b);
        }
    }

    int n0 = nbase + r0, n1 = n0 + 8;
    int d0 = (ntime[n0]*G_GRAPHS + batch[n0])*C1;
    int d1 = (ntime[n1]*G_GRAPHS + batch[n1])*C1;
    #pragma unroll
    for (int nt = 0; nt < 8; nt++) {
        int col = nh*64 + nt*8 + 2*c;
        float bx = sBias[col], by = sBias[col+1];
        *(float2*)&g_xgates[d0 + col] = make_float2(acc[nt][0] + bx, acc[nt][1] + by);
        *(float2*)&g_xgates[d1 + col] = make_float2(acc[nt][2] + bx, acc[nt][3] + by);
    }
}

// LSTM: 1 graph/block (512 blocks), Whh row in regs, xgates prefetch, fused FC.
__global__ void __launch_bounds__(256) k_lstm(
        const float* __restrict__ Whh, const float* __restrict__ Wfc,
        const float* __restrict__ bfc, float* __restrict__ out) {
    __shared__ float hhs[64];
    __shared__ float gates[C1];
    int t = threadIdx.x;
    int g = blockIdx.x;

    unsigned long long w2[32];
    const float4* wrow = (const float4*)(Whh + t*64);
    #pragma unroll
    for (int i = 0; i < 16; i++) {
        float4 w = wrow[i];
        w2[2*i]   = pk(w.x, w.y);
        w2[2*i+1] = pk(w.z, w.w);
    }
    if (t < 64) hhs[t] = 0.f;
    float c = 0.f;
    float xg_cur = g_xgates[g*C1 + t];
    __syncthreads();

    for (int step = 0; step < T_STEPS; step++) {
        float xg_next = 0.f;
        if (step + 1 < T_STEPS) xg_next = g_xgates[((step+1)*G_GRAPHS + g)*C1 + t];
        unsigned long long aA = 0ull, aB = 0ull;
        #pragma unroll
        for (int k2 = 0; k2 < 16; k2++) {
            ulonglong2 hv = *(const ulonglong2*)&hhs[k2*4];
            ffma2(aA, hv.x, w2[2*k2]);
            ffma2(aB, hv.y, w2[2*k2+1]);
        }
        float2 a = unpk(aA), b = unpk(aB);
        gates[t] = xg_cur + a.x + a.y + b.x + b.y;
        __syncthreads();
        if (t < 64) {
            float ig = gates[t],       fg = gates[64 + t];
            float gg = gates[128 + t], og = gates[192 + t];
            c = sigf(fg)*c + sigf(ig)*tanhf(gg);
            hhs[t] = sigf(og)*tanhf(c);
        }
        __syncthreads();
        xg_cur = xg_next;
    }
    if (t < OUT_DIM) {
        float acc = bfc[t];
        #pragma unroll 8
        for (int k = 0; k < 64; k++) acc += hhs[k] * Wfc[k*OUT_DIM + t];
        out[g*OUT_DIM + t] = acc;
    }
}

// ---------------- launch ----------------
static const int SMEM_P2 = (2048 + P2N*H1STR + 64 + 64 + 128 + 128) * 4;   // 43008 B
static const int SMEM_XG = (XGN*H2STR + 256 + 64 + 64 + 32) * 4;           // 10368 B

extern "C" void kernel_launch(void* const* d_in, const int* in_sizes, int n_in,
                              void* d_out, int out_size) {
    const float* x    = (const float*)d_in[0];
    const int*   ei   = (const int*)  d_in[1];
    const int*   batch= (const int*)  d_in[2];
    const int*   ntime= (const int*)  d_in[3];
    const float* W1   = (const float*)d_in[4];
    const float* as1  = (const float*)d_in[5];
    const float* ad1  = (const float*)d_in[6];
    const float* b1   = (const float*)d_in[7];
    const float* g1   = (const float*)d_in[8];
    const float* be1  = (const float*)d_in[9];
    const float* W2   = (const float*)d_in[10];
    const float* as2  = (const float*)d_in[11];
    const float* ad2  = (const float*)d_in[12];
    const float* b2   = (const float*)d_in[13];
    const float* g2   = (const float*)d_in[14];
    const float* be2  = (const float*)d_in[15];
    const float* Wih  = (const float*)d_in[16];
    const float* Whh  = (const float*)d_in[17];
    const float* bih  = (const float*)d_in[18];
    const float* bhh  = (const float*)d_in[19];
    const float* Wfc  = (const float*)d_in[20];
    const float* bfc  = (const float*)d_in[21];
    float* out = (float*)d_out;

    cudaFuncSetAttribute(k_proj2f,  cudaFuncAttributeMaxDynamicSharedMemorySize, SMEM_P2);
    cudaFuncSetAttribute(k_xgates2, cudaFuncAttributeMaxDynamicSharedMemorySize, SMEM_XG);

    void *p_xagg, *p_acc2, *p_den2;
    cudaGetSymbolAddress(&p_xagg, g_xagg);
    cudaGetSymbolAddress(&p_acc2, g_accum2);
    cudaGetSymbolAddress(&p_den2, g_denom2);
    cudaMemsetAsync(p_xagg, 0, sizeof(float)*N_NODES*32);
    cudaMemsetAsync(p_acc2, 0, sizeof(float)*N_NODES*HID);
    cudaMemsetAsync(p_den2, 0, sizeof(float)*N_NODES);

    k_prep2  <<<N_NODES/256, 256>>>(W1, as1, ad1, W2, Wih, x);            // launch 1
    k_esum1  <<<(EHALF + 255)/256, 256>>>(ei);                            // launch 2
    k_proj2f <<<N_NODES/P2N, 256, SMEM_P2>>>(W1, b1, g1, be1, as2, ad2);  // launch 3
    k_esum2  <<<(EHALF*8 + 255)/256, 256>>>(ei);                          // launch 4 (profiled)
    k_xgates2<<<N_NODES/XGN, 256, SMEM_XG>>>(bih, bhh, b2, g2, be2, batch, ntime);
    k_lstm   <<<G_GRAPHS, 256>>>(Whh, Wfc, bfc, out);
}

// round 16
// speedup vs baseline: 1.0116x; 1.0116x over previous
#include <cuda_runtime.h>
#include <math.h>
#include <stdint.h>

#define N_NODES 25600
#define N_EDGES 204800
#define ETOT    (N_EDGES + N_NODES)   // 230400
#define EHALF   (ETOT/2)              // 115200  (< N_EDGES, so edge A is never a self-loop)
#define IN_CH   6
#define HID     64
#define HEADS   4
#define C1      (HEADS*HID)           // 256
#define G_GRAPHS 512
#define T_STEPS  50
#define OUT_DIM  30
#define NEG_SLOPE 0.2f
#define BN_INV 0.9999950000374996f    // 1/sqrt(1+1e-5)

// ---------------- scratch ----------------
// one contiguous zeroed region: xagg [N*32] | accum2 [N*64] | denom2 [N]
#define ZBUF_FLOATS (N_NODES*97)
#define ACC2_OFF    (N_NODES*32)
#define DEN2_OFF    (N_NODES*96)
__device__ __align__(16) float g_zbuf[ZBUF_FLOATS];
__device__ __align__(16) float g_x8[N_NODES*8];
__device__ __align__(16) float g_asrc1[N_NODES*4];
__device__ __align__(16) float g_adst1[N_NODES*4];
__device__ __align__(16) float g_hproj2[N_NODES*HID];
__device__ float g_asrc2[N_NODES];
__device__ float g_adst2[N_NODES];
__device__ __align__(16) float g_xgates[N_NODES*C1];  // (t, g, 256)
__device__ __align__(16) uint32_t g_W2t[256*64];      // tf32 bits, [k][j]
__device__ __align__(16) uint32_t g_WihT[64*256];     // tf32 bits, [k][j] (Wih^T)

// ---------------- helpers ----------------
__device__ __forceinline__ float lrelu(float v) { return v > 0.f ? v : NEG_SLOPE*v; }
__device__ __forceinline__ float eluf(float v)  { return v > 0.f ? v : (__expf(v) - 1.f); }
__device__ __forceinline__ float sigf(float v)  { return 1.f/(1.f+expf(-v)); }

__device__ __forceinline__ void redAdd4(float* addr, float a, float b, float c, float d) {
    asm volatile("red.global.add.v4.f32 [%0], {%1,%2,%3,%4};"
                 :: "l"(addr), "f"(a), "f"(b), "f"(c), "f"(d) : "memory");
}
__device__ __forceinline__ void ffma2(unsigned long long& d, unsigned long long a,
                                      unsigned long long b) {
    asm("fma.rn.f32x2 %0, %1, %2, %0;" : "+l"(d) : "l"(a), "l"(b));
}
__device__ __forceinline__ unsigned long long pk(float a, float b) {
    unsigned long long r;
    asm("mov.b64 %0, {%1, %2};" : "=l"(r) : "f"(a), "f"(b));
    return r;
}
__device__ __forceinline__ float2 unpk(unsigned long long v) {
    float2 r;
    asm("mov.b64 {%0, %1}, %2;" : "=f"(r.x), "=f"(r.y) : "l"(v));
    return r;
}
__device__ __forceinline__ uint32_t f2tf32(float v) {
    uint32_t r;
    asm("cvt.rna.tf32.f32 %0, %1;" : "=r"(r) : "f"(v));
    return r;
}
// m16n8k8 tf32 MMA, fp32 accumulate (in-place)
__device__ __forceinline__ void mma_tf32(float* d, const uint32_t* a, const uint32_t* b) {
    asm("mma.sync.aligned.m16n8k8.row.col.f32.tf32.tf32.f32 "
        "{%0,%1,%2,%3},{%4,%5,%6,%7},{%8,%9},{%0,%1,%2,%3};"
        : "+f"(d[0]), "+f"(d[1]), "+f"(d[2]), "+f"(d[3])
        : "r"(a[0]), "r"(a[1]), "r"(a[2]), "r"(a[3]), "r"(b[0]), "r"(b[1]));
}

// ---------------- kernels ----------------
// merged prep: wsrc/wdst in smem (per-block redundant), weight conversion, att1 dots.
__global__ void k_prep2(const float* __restrict__ W1, const float* __restrict__ as1,
                        const float* __restrict__ ad1,
                        const float* __restrict__ W2, const float* __restrict__ Wih,
                        const float* __restrict__ x) {
    __shared__ float swsrc[24], swdst[24];
    int t = threadIdx.x;
    int i = blockIdx.x*256 + t;

    if (i < 16384) {
        g_W2t[i] = f2tf32(W2[i]);                  // layout already [k][64]
        int j = i >> 6, k = i & 63;                // Wih is [j][k]
        g_WihT[k*256 + j] = f2tf32(Wih[i]);        // -> [k][256]
    }
    if (t < 24) {
        int k = t >> 2, h = t & 3;
        float s = 0.f;
        for (int c = 0; c < 64; c++) s += W1[k*C1 + h*64 + c] * as1[h*64 + c];
        swsrc[t] = s;
    } else if (t >= 32 && t < 56) {
        int q = t - 32, k = q >> 2, h = q & 3;
        float s = 0.f;
        for (int c = 0; c < 64; c++) s += W1[k*C1 + h*64 + c] * ad1[h*64 + c];
        swdst[q] = s;
    }
    __syncthreads();

    int n = i;
    float2 xa = *(const float2*)&x[n*6];
    float2 xb = *(const float2*)&x[n*6 + 2];
    float2 xc = *(const float2*)&x[n*6 + 4];
    float xv[6] = {xa.x, xa.y, xb.x, xb.y, xc.x, xc.y};
    float s[4] = {0,0,0,0}, d[4] = {0,0,0,0};
    #pragma unroll
    for (int k = 0; k < 6; k++) {
        #pragma unroll
        for (int h = 0; h < 4; h++) {
            s[h] += xv[k]*swsrc[k*4+h];
            d[h] += xv[k]*swdst[k*4+h];
        }
    }
    *(float4*)&g_asrc1[n*4] = make_float4(s[0],s[1],s[2],s[3]);
    *(float4*)&g_adst1[n*4] = make_float4(d[0],d[1],d[2],d[3]);
    *(float4*)&g_x8[n*8]     = make_float4(xv[0],xv[1],xv[2],xv[3]);
    *(float4*)&g_x8[n*8 + 4] = make_float4(xv[4],xv[5],0.f,0.f);
}

// 2 edges per thread; ALL loads issued before the first red (MLP-friendly).
__global__ void k_esum1(const int* __restrict__ ei) {
    int e0 = blockIdx.x*blockDim.x + threadIdx.x;
    if (e0 >= EHALF) return;
    int eB = e0 + EHALF;
    // edge A always a real edge (EHALF < N_EDGES)
    int sA = ei[e0], dA = ei[N_EDGES + e0];
    int sB, dB;
    if (eB < N_EDGES) { sB = ei[eB]; dB = ei[N_EDGES + eB]; } else { sB = dB = eB - N_EDGES; }

    float4 asA = *(const float4*)&g_asrc1[sA*4];
    float4 adA = *(const float4*)&g_adst1[dA*4];
    float4 asB = *(const float4*)&g_asrc1[sB*4];
    float4 adB = *(const float4*)&g_adst1[dB*4];
    float4 xaA = *(const float4*)&g_x8[sA*8];
    float4 xbA = *(const float4*)&g_x8[sA*8 + 4];
    float4 xaB = *(const float4*)&g_x8[sB*8];
    float4 xbB = *(const float4*)&g_x8[sB*8 + 4];

    float exA[4], exB[4];
    exA[0] = __expf(lrelu(asA.x + adA.x));
    exA[1] = __expf(lrelu(asA.y + adA.y));
    exA[2] = __expf(lrelu(asA.z + adA.z));
    exA[3] = __expf(lrelu(asA.w + adA.w));
    exB[0] = __expf(lrelu(asB.x + adB.x));
    exB[1] = __expf(lrelu(asB.y + adB.y));
    exB[2] = __expf(lrelu(asB.z + adB.z));
    exB[3] = __expf(lrelu(asB.w + adB.w));

    float* baseA = &g_zbuf[dA*32];
    float* baseB = &g_zbuf[dB*32];
    #pragma unroll
    for (int h = 0; h < 4; h++) {
        float w = exA[h];
        redAdd4(baseA + h*8,     w*xaA.x, w*xaA.y, w*xaA.z, w*xaA.w);
        redAdd4(baseA + h*8 + 4, w*xbA.x, w*xbA.y, w,       0.f);
    }
    #pragma unroll
    for (int h = 0; h < 4; h++) {
        float w = exB[h];
        redAdd4(baseB + h*8,     w*xaB.x, w*xaB.y, w*xaB.z, w*xaB.w);
        redAdd4(baseB + h*8 + 4, w*xbB.x, w*xbB.y, w,       0.f);
    }
}

// fused GAT2 projection via tf32 MMA. 32 nodes/block, 4 CTAs/SM,
// fully unrolled K loop (immediate offsets), B frags from L1.
#define P2N 32
#define H1STR 260          // (4r + k) % 32 -> conflict-free A frags
__global__ void __launch_bounds__(256, 4) k_proj2f(
        const float* __restrict__ W1, const float* __restrict__ b1,
        const float* __restrict__ g1, const float* __restrict__ be1,
        const float* __restrict__ as2, const float* __restrict__ ad2) {
    extern __shared__ float sm[];
    float* sW1p = sm;                      // [256][8]: {w0..w5, A, C} f32 = 2048
    float* h1s  = sW1p + 2048;             // [32][260] tf32 bits
    float* sAs  = h1s + P2N*H1STR;         // 64
    float* sAd  = sAs + 64;                // 64
    float* sS   = sAd + 64;                // 128
    float* sD   = sS + 128;                // 128
    int t = threadIdx.x;
    int nbase = blockIdx.x * P2N;

    for (int i = t; i < 2048; i += 256) {
        int c = i >> 3, r = i & 7;
        float v;
        if (r < 6)       v = W1[r*C1 + c];
        else if (r == 6) v = g1[c]*BN_INV;
        else { float A = g1[c]*BN_INV; v = A*b1[c] + be1[c]; }
        sW1p[i] = v;
    }
    if (t < 64)            sAs[t] = as2[t];
    else if (t < 128)      sAd[t-64] = ad2[t-64];
    __syncthreads();

    // phase 1: thread (nl, q) computes h1 cols [q*32, q*32+32) of node nl (head q>>1)
    {
        int nl = t & 31, q = t >> 5;
        int n  = nbase + nl;
        int h  = q >> 1;
        float4 v0 = *(const float4*)&g_zbuf[n*32 + h*8];
        float4 v1 = *(const float4*)&g_zbuf[n*32 + h*8 + 4];
        float inv = 1.f / v1.z;
        float x0 = v0.x*inv, x1 = v0.y*inv, x2 = v0.z*inv;
        float x3 = v0.w*inv, x4 = v1.x*inv, x5 = v1.y*inv;
        #pragma unroll 8
        for (int c2 = 0; c2 < 32; c2++) {
            int c = q*32 + c2;
            float4 wa = *(const float4*)&sW1p[c*8];
            float4 wb = *(const float4*)&sW1p[c*8 + 4];
            float dot = x0*wa.x + x1*wa.y + x2*wa.z + x3*wa.w + x4*wb.x + x5*wb.y;
            h1s[nl*H1STR + c] = __uint_as_float(f2tf32(eluf(dot*wb.z + wb.w)));
        }
    }
    __syncthreads();

    // phase 2: MMA. warp w: mt=w&1 (16 nodes), nq=w>>1 (16 cols = 2 n-tiles)
    const uint32_t* h1u = (const uint32_t*)h1s;
    int w = t >> 5, l = t & 31;
    int g = l >> 2, c = l & 3;
    int mt = w & 1, nq = w >> 1;
    int r0 = mt*16 + g;

    float acc[2][4];
    #pragma unroll
    for (int nt = 0; nt < 2; nt++) { acc[nt][0]=0; acc[nt][1]=0; acc[nt][2]=0; acc[nt][3]=0; }

    const uint32_t* ap = h1u + r0*H1STR + c;
    const uint32_t* wp = &g_W2t[c*64 + nq*16 + g];
    #pragma unroll
    for (int ks = 0; ks < 32; ks++) {
        const int kb = ks*8;
        uint32_t a[4];
        a[0] = ap[kb];
        a[1] = ap[kb + 8*H1STR];
        a[2] = ap[kb + 4];
        a[3] = ap[kb + 8*H1STR + 4];
        #pragma unroll
        for (int nt = 0; nt < 2; nt++) {
            uint32_t b[2];
            b[0] = __ldg(&wp[kb*64 + nt*8]);
            b[1] = __ldg(&wp[(kb + 4)*64 + nt*8]);
            mma_tf32(acc[nt], a, b);
        }
    }

    // epilogue: store hproj2 + att2 partial dots
    float s0 = 0.f, d0 = 0.f, s1 = 0.f, d1 = 0.f;
    int n0 = nbase + r0, n1 = n0 + 8;
    #pragma unroll
    for (int nt = 0; nt < 2; nt++) {
        int col = nq*16 + nt*8 + 2*c;
        *(float2*)&g_hproj2[n0*64 + col] = make_float2(acc[nt][0], acc[nt][1]);
        *(float2*)&g_hproj2[n1*64 + col] = make_float2(acc[nt][2], acc[nt][3]);
        s0 += acc[nt][0]*sAs[col] + acc[nt][1]*sAs[col+1];
        d0 += acc[nt][0]*sAd[col] + acc[nt][1]*sAd[col+1];
        s1 += acc[nt][2]*sAs[col] + acc[nt][3]*sAs[col+1];
        d1 += acc[nt][2]*sAd[col] + acc[nt][3]*sAd[col+1];
    }
    #pragma unroll
    for (int m = 1; m < 4; m <<= 1) {
        s0 += __shfl_xor_sync(~0u, s0, m);
        d0 += __shfl_xor_sync(~0u, d0, m);
        s1 += __shfl_xor_sync(~0u, s1, m);
        d1 += __shfl_xor_sync(~0u, d1, m);
    }
    if (c == 0) {
        sS[r0*4 + nq] = s0;     sD[r0*4 + nq] = d0;
        sS[(r0+8)*4 + nq] = s1; sD[(r0+8)*4 + nq] = d1;
    }
    __syncthreads();
    if (t < P2N) {
        float ss = sS[t*4] + sS[t*4+1] + sS[t*4+2] + sS[t*4+3];
        float dd = sD[t*4] + sD[t*4+1] + sD[t*4+2] + sD[t*4+3];
        g_asrc2[nbase + t] = ss;
        g_adst2[nbase + t] = dd;
    }
}

// 8 threads/edge, 2 edges per thread; ALL loads before the first red.
__global__ void k_esum2(const int* __restrict__ ei) {
    int gt = blockIdx.x*blockDim.x + threadIdx.x;
    int e0 = gt >> 3, q = gt & 7;
    if (e0 >= EHALF) return;
    int eB = e0 + EHALF;
    int sA = ei[e0], dA = ei[N_EDGES + e0];
    int sB, dB;
    if (eB < N_EDGES) { sB = ei[eB]; dB = ei[N_EDGES + eB]; } else { sB = dB = eB - N_EDGES; }

    float scA = g_asrc2[sA] + g_adst2[dA];
    float scB = g_asrc2[sB] + g_adst2[dB];
    int c = q*8;
    float4 vA1 = *(const float4*)&g_hproj2[sA*64 + c];
    float4 vA2 = *(const float4*)&g_hproj2[sA*64 + c + 4];
    float4 vB1 = *(const float4*)&g_hproj2[sB*64 + c];
    float4 vB2 = *(const float4*)&g_hproj2[sB*64 + c + 4];

    float exA = __expf(lrelu(scA));
    float exB = __expf(lrelu(scB));

    if (q == 0) {
        atomicAdd(&g_zbuf[DEN2_OFF + dA], exA);
        atomicAdd(&g_zbuf[DEN2_OFF + dB], exB);
    }
    redAdd4(&g_zbuf[ACC2_OFF + dA*64 + c],     vA1.x*exA, vA1.y*exA, vA1.z*exA, vA1.w*exA);
    redAdd4(&g_zbuf[ACC2_OFF + dA*64 + c + 4], vA2.x*exA, vA2.y*exA, vA2.z*exA, vA2.w*exA);
    redAdd4(&g_zbuf[ACC2_OFF + dB*64 + c],     vB1.x*exB, vB1.y*exB, vB1.z*exB, vB1.w*exB);
    redAdd4(&g_zbuf[ACC2_OFF + dB*64 + c + 4], vB2.x*exB, vB2.y*exB, vB2.z*exB, vB2.w*exB);
}

// fused: h2 staged once as tf32; xgates = h2@Wih^T + biases via tf32 MMA (scattered rows).
#define XGN 32
#define H2STR 68           // (4r + k) % 32 -> conflict-free A frags
__global__ void __launch_bounds__(256, 4) k_xgates2(
        const float* __restrict__ bih, const float* __restrict__ bhh,
        const float* __restrict__ b2, const float* __restrict__ g2,
        const float* __restrict__ be2,
        const int* __restrict__ batch, const int* __restrict__ ntime) {
    extern __shared__ float sm[];
    float* h2s   = sm;                    // [32][68] tf32 bits
    float* sBias = h2s + XGN*H2STR;       // 256
    float* sA2   = sBias + 256;           // 64
    float* sC2   = sA2 + 64;              // 64
    float* sInv  = sC2 + 64;              // 32
    int t = threadIdx.x;
    int nbase = blockIdx.x * XGN;

    sBias[t] = bih[t] + bhh[t];
    if (t < 64) {
        float A = g2[t]*BN_INV;
        sA2[t] = A;
        sC2[t] = A*b2[t] + be2[t];
    } else if (t >= 128 && t < 160) {
        sInv[t-128] = 1.f / g_zbuf[DEN2_OFF + nbase + (t-128)];
    }
    __syncthreads();

    for (int i = t; i < XGN*64; i += 256) {
        int nn = i >> 6, k = i & 63;
        float v = g_zbuf[ACC2_OFF + (nbase + nn)*64 + k] * sInv[nn];
        h2s[nn*H2STR + k] = __uint_as_float(f2tf32(eluf(v*sA2[k] + sC2[k])));
    }
    __syncthreads();

    const uint32_t* h2u = (const uint32_t*)h2s;
    int w = t >> 5, l = t & 31;
    int g = l >> 2, c = l & 3;
    int mt = w & 1, nh = w >> 1;   // nh in 0..3: 64-col group
    int r0 = mt*16 + g;

    float acc[8][4];
    #pragma unroll
    for (int nt = 0; nt < 8; nt++) { acc[nt][0]=0; acc[nt][1]=0; acc[nt][2]=0; acc[nt][3]=0; }

    const uint32_t* ap = h2u + r0*H2STR + c;
    const uint32_t* wp = &g_WihT[c*256 + nh*64 + g];
    #pragma unroll
    for (int ks = 0; ks < 8; ks++) {
        const int kb = ks*8;
        uint32_t a[4];
        a[0] = ap[kb];
        a[1] = ap[kb + 8*H2STR];
        a[2] = ap[kb + 4];
        a[3] = ap[kb + 8*H2STR + 4];
        #pragma unroll
        for (int nt = 0; nt < 8; nt++) {
            uint32_t b[2];
            b[0] = __ldg(&wp[kb*256 + nt*8]);
            b[1] = __ldg(&wp[(kb + 4)*256 + nt*8]);
            mma_tf32(acc[nt], a, b);
        }
    }

    int n0 = nbase + r0, n1 = n0 + 8;
    int d0 = (ntime[n0]*G_GRAPHS + batch[n0])*C1;
    int d1 = (ntime[n1]*G_GRAPHS + batch[n1])*C1;
    #pragma unroll
    for (int nt = 0; nt < 8; nt++) {
        int col = nh*64 + nt*8 + 2*c;
        float bx = sBias[col], by = sBias[col+1];
        *(float2*)&g_xgates[d0 + col] = make_float2(acc[nt][0] + bx, acc[nt][1] + by);
        *(float2*)&g_xgates[d1 + col] = make_float2(acc[nt][2] + bx, acc[nt][3] + by);
    }
}

// LSTM: 1 graph/block (512 blocks), Whh row in regs, xgates prefetch, fused FC.
__global__ void __launch_bounds__(256) k_lstm(
        const float* __restrict__ Whh, const float* __restrict__ Wfc,
        const float* __restrict__ bfc, float* __restrict__ out) {
    __shared__ float hhs[64];
    __shared__ float gates[C1];
    int t = threadIdx.x;
    int g = blockIdx.x;

    unsigned long long w2[32];
    const float4* wrow = (const float4*)(Whh + t*64);
    #pragma unroll
    for (int i = 0; i < 16; i++) {
        float4 w = wrow[i];
        w2[2*i]   = pk(w.x, w.y);
        w2[2*i+1] = pk(w.z, w.w);
    }
    if (t < 64) hhs[t] = 0.f;
    float c = 0.f;
    float xg_cur = g_xgates[g*C1 + t];
    __syncthreads();

    for (int step = 0; step < T_STEPS; step++) {
        float xg_next = 0.f;
        if (step + 1 < T_STEPS) xg_next = g_xgates[((step+1)*G_GRAPHS + g)*C1 + t];
        unsigned long long aA = 0ull, aB = 0ull;
        #pragma unroll
        for (int k2 = 0; k2 < 16; k2++) {
            ulonglong2 hv = *(const ulonglong2*)&hhs[k2*4];
            ffma2(aA, hv.x, w2[2*k2]);
            ffma2(aB, hv.y, w2[2*k2+1]);
        }
        float2 a = unpk(aA), b = unpk(aB);
        gates[t] = xg_cur + a.x + a.y + b.x + b.y;
        __syncthreads();
        if (t < 64) {
            float ig = gates[t],       fg = gates[64 + t];
            float gg = gates[128 + t], og = gates[192 + t];
            c = sigf(fg)*c + sigf(ig)*tanhf(gg);
            hhs[t] = sigf(og)*tanhf(c);
        }
        __syncthreads();
        xg_cur = xg_next;
    }
    if (t < OUT_DIM) {
        float acc = bfc[t];
        #pragma unroll 8
        for (int k = 0; k < 64; k++) acc += hhs[k] * Wfc[k*OUT_DIM + t];
        out[g*OUT_DIM + t] = acc;
    }
}

// ---------------- launch ----------------
static const int SMEM_P2 = (2048 + P2N*H1STR + 64 + 64 + 128 + 128) * 4;   // 43008 B
static const int SMEM_XG = (XGN*H2STR + 256 + 64 + 64 + 32) * 4;           // 10368 B

extern "C" void kernel_launch(void* const* d_in, const int* in_sizes, int n_in,
                              void* d_out, int out_size) {
    const float* x    = (const float*)d_in[0];
    const int*   ei   = (const int*)  d_in[1];
    const int*   batch= (const int*)  d_in[2];
    const int*   ntime= (const int*)  d_in[3];
    const float* W1   = (const float*)d_in[4];
    const float* as1  = (const float*)d_in[5];
    const float* ad1  = (const float*)d_in[6];
    const float* b1   = (const float*)d_in[7];
    const float* g1   = (const float*)d_in[8];
    const float* be1  = (const float*)d_in[9];
    const float* W2   = (const float*)d_in[10];
    const float* as2  = (const float*)d_in[11];
    const float* ad2  = (const float*)d_in[12];
    const float* b2   = (const float*)d_in[13];
    const float* g2   = (const float*)d_in[14];
    const float* be2  = (const float*)d_in[15];
    const float* Wih  = (const float*)d_in[16];
    const float* Whh  = (const float*)d_in[17];
    const float* bih  = (const float*)d_in[18];
    const float* bhh  = (const float*)d_in[19];
    const float* Wfc  = (const float*)d_in[20];
    const float* bfc  = (const float*)d_in[21];
    float* out = (float*)d_out;

    cudaFuncSetAttribute(k_proj2f,  cudaFuncAttributeMaxDynamicSharedMemorySize, SMEM_P2);
    cudaFuncSetAttribute(k_xgates2, cudaFuncAttributeMaxDynamicSharedMemorySize, SMEM_XG);

    void* p_zbuf;
    cudaGetSymbolAddress(&p_zbuf, g_zbuf);
    cudaMemsetAsync(p_zbuf, 0, sizeof(float)*ZBUF_FLOATS);

    k_prep2  <<<N_NODES/256, 256>>>(W1, as1, ad1, W2, Wih, x);            // launch 1
    k_esum1  <<<(EHALF + 255)/256, 256>>>(ei);                            // launch 2
    k_proj2f <<<N_NODES/P2N, 256, SMEM_P2>>>(W1, b1, g1, be1, as2, ad2);  // launch 3
    k_esum2  <<<(EHALF*8 + 255)/256, 256>>>(ei);                          // launch 4 (profiled)
    k_xgates2<<<N_NODES/XGN, 256, SMEM_XG>>>(bih, bhh, b2, g2, be2, batch, ntime);
    k_lstm   <<<G_GRAPHS, 256>>>(Whh, Wfc, bfc, out);
}

// round 17
// speedup vs baseline: 1.0143x; 1.0027x over previous
#include <cuda_runtime.h>
#include <cuda_fp16.h>
#include <math.h>
#include <stdint.h>

#define N_NODES 25600
#define N_EDGES 204800
#define ETOT    (N_EDGES + N_NODES)   // 230400
#define EHALF   (ETOT/2)              // 115200  (< N_EDGES, so edge A is never a self-loop)
#define IN_CH   6
#define HID     64
#define HEADS   4
#define C1      (HEADS*HID)           // 256
#define G_GRAPHS 512
#define T_STEPS  50
#define OUT_DIM  30
#define NEG_SLOPE 0.2f
#define BN_INV 0.9999950000374996f    // 1/sqrt(1+1e-5)

// ---------------- scratch ----------------
// one contiguous zeroed region: xagg [N*32] | accum2 [N*64] | denom2 [N]
#define ZBUF_FLOATS (N_NODES*97)
#define ACC2_OFF    (N_NODES*32)
#define DEN2_OFF    (N_NODES*96)
__device__ __align__(16) float g_zbuf[ZBUF_FLOATS];
__device__ __align__(16) float g_x8[N_NODES*8];
__device__ __align__(16) float g_asrc1[N_NODES*4];
__device__ __align__(16) float g_adst1[N_NODES*4];
__device__ __align__(16) __half g_hproj2h[N_NODES*HID];   // fp16 V-path values
__device__ float g_asrc2[N_NODES];
__device__ float g_adst2[N_NODES];
__device__ __align__(16) float g_xgates[N_NODES*C1];  // (t, g, 256)
__device__ __align__(16) uint32_t g_W2t[256*64];      // tf32 bits, [k][j]
__device__ __align__(16) uint32_t g_WihT[64*256];     // tf32 bits, [k][j] (Wih^T)

// ---------------- helpers ----------------
__device__ __forceinline__ float lrelu(float v) { return v > 0.f ? v : NEG_SLOPE*v; }
__device__ __forceinline__ float eluf(float v)  { return v > 0.f ? v : (__expf(v) - 1.f); }
__device__ __forceinline__ float sigf(float v)  { return 1.f/(1.f+__expf(-v)); }

// no "memory" clobber: reds alias nothing read later in the same kernel
__device__ __forceinline__ void redAdd4(float* addr, float a, float b, float c, float d) {
    asm volatile("red.global.add.v4.f32 [%0], {%1,%2,%3,%4};"
                 :: "l"(addr), "f"(a), "f"(b), "f"(c), "f"(d));
}
__device__ __forceinline__ void ffma2(unsigned long long& d, unsigned long long a,
                                      unsigned long long b) {
    asm("fma.rn.f32x2 %0, %1, %2, %0;" : "+l"(d) : "l"(a), "l"(b));
}
__device__ __forceinline__ unsigned long long pk(float a, float b) {
    unsigned long long r;
    asm("mov.b64 %0, {%1, %2};" : "=l"(r) : "f"(a), "f"(b));
    return r;
}
__device__ __forceinline__ float2 unpk(unsigned long long v) {
    float2 r;
    asm("mov.b64 {%0, %1}, %2;" : "=f"(r.x), "=f"(r.y) : "l"(v));
    return r;
}
__device__ __forceinline__ uint32_t f2tf32(float v) {
    uint32_t r;
    asm("cvt.rna.tf32.f32 %0, %1;" : "=r"(r) : "f"(v));
    return r;
}
// m16n8k8 tf32 MMA, fp32 accumulate (in-place)
__device__ __forceinline__ void mma_tf32(float* d, const uint32_t* a, const uint32_t* b) {
    asm("mma.sync.aligned.m16n8k8.row.col.f32.tf32.tf32.f32 "
        "{%0,%1,%2,%3},{%4,%5,%6,%7},{%8,%9},{%0,%1,%2,%3};"
        : "+f"(d[0]), "+f"(d[1]), "+f"(d[2]), "+f"(d[3])
        : "r"(a[0]), "r"(a[1]), "r"(a[2]), "r"(a[3]), "r"(b[0]), "r"(b[1]));
}

// ---------------- kernels ----------------
// merged prep: wsrc/wdst in smem (per-block redundant), weight conversion, att1 dots.
__global__ void k_prep2(const float* __restrict__ W1, const float* __restrict__ as1,
                        const float* __restrict__ ad1,
                        const float* __restrict__ W2, const float* __restrict__ Wih,
                        const float* __restrict__ x) {
    __shared__ float swsrc[24], swdst[24];
    int t = threadIdx.x;
    int i = blockIdx.x*256 + t;

    if (i < 16384) {
        g_W2t[i] = f2tf32(W2[i]);                  // layout already [k][64]
        int j = i >> 6, k = i & 63;                // Wih is [j][k]
        g_WihT[k*256 + j] = f2tf32(Wih[i]);        // -> [k][256]
    }
    if (t < 24) {
        int k = t >> 2, h = t & 3;
        float s = 0.f;
        for (int c = 0; c < 64; c++) s += W1[k*C1 + h*64 + c] * as1[h*64 + c];
        swsrc[t] = s;
    } else if (t >= 32 && t < 56) {
        int q = t - 32, k = q >> 2, h = q & 3;
        float s = 0.f;
        for (int c = 0; c < 64; c++) s += W1[k*C1 + h*64 + c] * ad1[h*64 + c];
        swdst[q] = s;
    }
    __syncthreads();

    int n = i;
    float2 xa = *(const float2*)&x[n*6];
    float2 xb = *(const float2*)&x[n*6 + 2];
    float2 xc = *(const float2*)&x[n*6 + 4];
    float xv[6] = {xa.x, xa.y, xb.x, xb.y, xc.x, xc.y};
    float s[4] = {0,0,0,0}, d[4] = {0,0,0,0};
    #pragma unroll
    for (int k = 0; k < 6; k++) {
        #pragma unroll
        for (int h = 0; h < 4; h++) {
            s[h] += xv[k]*swsrc[k*4+h];
            d[h] += xv[k]*swdst[k*4+h];
        }
    }
    *(float4*)&g_asrc1[n*4] = make_float4(s[0],s[1],s[2],s[3]);
    *(float4*)&g_adst1[n*4] = make_float4(d[0],d[1],d[2],d[3]);
    *(float4*)&g_x8[n*8]     = make_float4(xv[0],xv[1],xv[2],xv[3]);
    *(float4*)&g_x8[n*8 + 4] = make_float4(xv[4],xv[5],0.f,0.f);
}

// 2 edges per thread; ALL loads issued before the first red (MLP-friendly).
__global__ void k_esum1(const int* __restrict__ ei) {
    int e0 = blockIdx.x*blockDim.x + threadIdx.x;
    if (e0 >= EHALF) return;
    int eB = e0 + EHALF;
    int sA = ei[e0], dA = ei[N_EDGES + e0];
    int sB, dB;
    if (eB < N_EDGES) { sB = ei[eB]; dB = ei[N_EDGES + eB]; } else { sB = dB = eB - N_EDGES; }

    float4 asA = *(const float4*)&g_asrc1[sA*4];
    float4 adA = *(const float4*)&g_adst1[dA*4];
    float4 asB = *(const float4*)&g_asrc1[sB*4];
    float4 adB = *(const float4*)&g_adst1[dB*4];
    float4 xaA = *(const float4*)&g_x8[sA*8];
    float4 xbA = *(const float4*)&g_x8[sA*8 + 4];
    float4 xaB = *(const float4*)&g_x8[sB*8];
    float4 xbB = *(const float4*)&g_x8[sB*8 + 4];

    float exA[4], exB[4];
    exA[0] = __expf(lrelu(asA.x + adA.x));
    exA[1] = __expf(lrelu(asA.y + adA.y));
    exA[2] = __expf(lrelu(asA.z + adA.z));
    exA[3] = __expf(lrelu(asA.w + adA.w));
    exB[0] = __expf(lrelu(asB.x + adB.x));
    exB[1] = __expf(lrelu(asB.y + adB.y));
    exB[2] = __expf(lrelu(asB.z + adB.z));
    exB[3] = __expf(lrelu(asB.w + adB.w));

    float* baseA = &g_zbuf[dA*32];
    float* baseB = &g_zbuf[dB*32];
    #pragma unroll
    for (int h = 0; h < 4; h++) {
        float w = exA[h];
        redAdd4(baseA + h*8,     w*xaA.x, w*xaA.y, w*xaA.z, w*xaA.w);
        redAdd4(baseA + h*8 + 4, w*xbA.x, w*xbA.y, w,       0.f);
    }
    #pragma unroll
    for (int h = 0; h < 4; h++) {
        float w = exB[h];
        redAdd4(baseB + h*8,     w*xaB.x, w*xaB.y, w*xaB.z, w*xaB.w);
        redAdd4(baseB + h*8 + 4, w*xbB.x, w*xbB.y, w,       0.f);
    }
}

// fused GAT2 projection via tf32 MMA. 32 nodes/block, 4 CTAs/SM,
// fully unrolled K loop (immediate offsets), B frags from L1. hproj2 stored fp16.
#define P2N 32
#define H1STR 260          // (4r + k) % 32 -> conflict-free A frags
__global__ void __launch_bounds__(256, 4) k_proj2f(
        const float* __restrict__ W1, const float* __restrict__ b1,
        const float* __restrict__ g1, const float* __restrict__ be1,
        const float* __restrict__ as2, const float* __restrict__ ad2) {
    extern __shared__ float sm[];
    float* sW1p = sm;                      // [256][8]: {w0..w5, A, C} f32 = 2048
    float* h1s  = sW1p + 2048;             // [32][260] tf32 bits
    float* sAs  = h1s + P2N*H1STR;         // 64
    float* sAd  = sAs + 64;                // 64
    float* sS   = sAd + 64;                // 128
    float* sD   = sS + 128;                // 128
    int t = threadIdx.x;
    int nbase = blockIdx.x * P2N;

    for (int i = t; i < 2048; i += 256) {
        int c = i >> 3, r = i & 7;
        float v;
        if (r < 6)       v = W1[r*C1 + c];
        else if (r == 6) v = g1[c]*BN_INV;
        else { float A = g1[c]*BN_INV; v = A*b1[c] + be1[c]; }
        sW1p[i] = v;
    }
    if (t < 64)            sAs[t] = as2[t];
    else if (t < 128)      sAd[t-64] = ad2[t-64];
    __syncthreads();

    // phase 1: thread (nl, q) computes h1 cols [q*32, q*32+32) of node nl (head q>>1)
    {
        int nl = t & 31, q = t >> 5;
        int n  = nbase + nl;
        int h  = q >> 1;
        float4 v0 = *(const float4*)&g_zbuf[n*32 + h*8];
        float4 v1 = *(const float4*)&g_zbuf[n*32 + h*8 + 4];
        float inv = 1.f / v1.z;
        float x0 = v0.x*inv, x1 = v0.y*inv, x2 = v0.z*inv;
        float x3 = v0.w*inv, x4 = v1.x*inv, x5 = v1.y*inv;
        #pragma unroll 8
        for (int c2 = 0; c2 < 32; c2++) {
            int c = q*32 + c2;
            float4 wa = *(const float4*)&sW1p[c*8];
            float4 wb = *(const float4*)&sW1p[c*8 + 4];
            float dot = x0*wa.x + x1*wa.y + x2*wa.z + x3*wa.w + x4*wb.x + x5*wb.y;
            h1s[nl*H1STR + c] = __uint_as_float(f2tf32(eluf(dot*wb.z + wb.w)));
        }
    }
    __syncthreads();

    // phase 2: MMA. warp w: mt=w&1 (16 nodes), nq=w>>1 (16 cols = 2 n-tiles)
    const uint32_t* h1u = (const uint32_t*)h1s;
    int w = t >> 5, l = t & 31;
    int g = l >> 2, c = l & 3;
    int mt = w & 1, nq = w >> 1;
    int r0 = mt*16 + g;

    float acc[2][4];
    #pragma unroll
    for (int nt = 0; nt < 2; nt++) { acc[nt][0]=0; acc[nt][1]=0; acc[nt][2]=0; acc[nt][3]=0; }

    const uint32_t* ap = h1u + r0*H1STR + c;
    const uint32_t* wp = &g_W2t[c*64 + nq*16 + g];
    #pragma unroll
    for (int ks = 0; ks < 32; ks++) {
        const int kb = ks*8;
        uint32_t a[4];
        a[0] = ap[kb];
        a[1] = ap[kb + 8*H1STR];
        a[2] = ap[kb + 4];
        a[3] = ap[kb + 8*H1STR + 4];
        #pragma unroll
        for (int nt = 0; nt < 2; nt++) {
            uint32_t b[2];
            b[0] = __ldg(&wp[kb*64 + nt*8]);
            b[1] = __ldg(&wp[(kb + 4)*64 + nt*8]);
            mma_tf32(acc[nt], a, b);
        }
    }

    // epilogue: store hproj2 (fp16) + att2 partial dots (fp32)
    float s0 = 0.f, d0 = 0.f, s1 = 0.f, d1 = 0.f;
    int n0 = nbase + r0, n1 = n0 + 8;
    #pragma unroll
    for (int nt = 0; nt < 2; nt++) {
        int col = nq*16 + nt*8 + 2*c;
        *(__half2*)&g_hproj2h[n0*64 + col] = __floats2half2_rn(acc[nt][0], acc[nt][1]);
        *(__half2*)&g_hproj2h[n1*64 + col] = __floats2half2_rn(acc[nt][2], acc[nt][3]);
        s0 += acc[nt][0]*sAs[col] + acc[nt][1]*sAs[col+1];
        d0 += acc[nt][0]*sAd[col] + acc[nt][1]*sAd[col+1];
        s1 += acc[nt][2]*sAs[col] + acc[nt][3]*sAs[col+1];
        d1 += acc[nt][2]*sAd[col] + acc[nt][3]*sAd[col+1];
    }
    #pragma unroll
    for (int m = 1; m < 4; m <<= 1) {
        s0 += __shfl_xor_sync(~0u, s0, m);
        d0 += __shfl_xor_sync(~0u, d0, m);
        s1 += __shfl_xor_sync(~0u, s1, m);
        d1 += __shfl_xor_sync(~0u, d1, m);
    }
    if (c == 0) {
        sS[r0*4 + nq] = s0;     sD[r0*4 + nq] = d0;
        sS[(r0+8)*4 + nq] = s1; sD[(r0+8)*4 + nq] = d1;
    }
    __syncthreads();
    if (t < P2N) {
        float ss = sS[t*4] + sS[t*4+1] + sS[t*4+2] + sS[t*4+3];
        float dd = sD[t*4] + sD[t*4+1] + sD[t*4+2] + sD[t*4+3];
        g_asrc2[nbase + t] = ss;
        g_adst2[nbase + t] = dd;
    }
}

// 8 threads/edge, 2 edges per thread; fp16 gathers (16B/thread/edge); loads before reds.
__global__ void k_esum2(const int* __restrict__ ei) {
    int gt = blockIdx.x*blockDim.x + threadIdx.x;
    int e0 = gt >> 3, q = gt & 7;
    if (e0 >= EHALF) return;
    int eB = e0 + EHALF;
    int sA = ei[e0], dA = ei[N_EDGES + e0];
    int sB, dB;
    if (eB < N_EDGES) { sB = ei[eB]; dB = ei[N_EDGES + eB]; } else { sB = dB = eB - N_EDGES; }

    float scA = g_asrc2[sA] + g_adst2[dA];
    float scB = g_asrc2[sB] + g_adst2[dB];
    int c = q*8;
    uint4 hA = *(const uint4*)&g_hproj2h[sA*64 + c];   // 8 halves
    uint4 hB = *(const uint4*)&g_hproj2h[sB*64 + c];

    float exA = __expf(lrelu(scA));
    float exB = __expf(lrelu(scB));

    float2 a0 = __half22float2(*(__half2*)&hA.x);
    float2 a1 = __half22float2(*(__half2*)&hA.y);
    float2 a2 = __half22float2(*(__half2*)&hA.z);
    float2 a3 = __half22float2(*(__half2*)&hA.w);
    float2 b0 = __half22float2(*(__half2*)&hB.x);
    float2 b1 = __half22float2(*(__half2*)&hB.y);
    float2 b2 = __half22float2(*(__half2*)&hB.z);
    float2 b3 = __half22float2(*(__half2*)&hB.w);

    if (q == 0) {
        atomicAdd(&g_zbuf[DEN2_OFF + dA], exA);
        atomicAdd(&g_zbuf[DEN2_OFF + dB], exB);
    }
    redAdd4(&g_zbuf[ACC2_OFF + dA*64 + c],     a0.x*exA, a0.y*exA, a1.x*exA, a1.y*exA);
    redAdd4(&g_zbuf[ACC2_OFF + dA*64 + c + 4], a2.x*exA, a2.y*exA, a3.x*exA, a3.y*exA);
    redAdd4(&g_zbuf[ACC2_OFF + dB*64 + c],     b0.x*exB, b0.y*exB, b1.x*exB, b1.y*exB);
    redAdd4(&g_zbuf[ACC2_OFF + dB*64 + c + 4], b2.x*exB, b2.y*exB, b3.x*exB, b3.y*exB);
}

// fused: h2 staged once as tf32; xgates = h2@Wih^T + biases via tf32 MMA (scattered rows).
#define XGN 32
#define H2STR 68           // (4r + k) % 32 -> conflict-free A frags
__global__ void __launch_bounds__(256, 4) k_xgates2(
        const float* __restrict__ bih, const float* __restrict__ bhh,
        const float* __restrict__ b2, const float* __restrict__ g2,
        const float* __restrict__ be2,
        const int* __restrict__ batch, const int* __restrict__ ntime) {
    extern __shared__ float sm[];
    float* h2s   = sm;                    // [32][68] tf32 bits
    float* sBias = h2s + XGN*H2STR;       // 256
    float* sA2   = sBias + 256;           // 64
    float* sC2   = sA2 + 64;              // 64
    float* sInv  = sC2 + 64;              // 32
    int t = threadIdx.x;
    int nbase = blockIdx.x * XGN;

    sBias[t] = bih[t] + bhh[t];
    if (t < 64) {
        float A = g2[t]*BN_INV;
        sA2[t] = A;
        sC2[t] = A*b2[t] + be2[t];
    } else if (t >= 128 && t < 160) {
        sInv[t-128] = 1.f / g_zbuf[DEN2_OFF + nbase + (t-128)];
    }
    __syncthreads();

    for (int i = t; i < XGN*64; i += 256) {
        int nn = i >> 6, k = i & 63;
        float v = g_zbuf[ACC2_OFF + (nbase + nn)*64 + k] * sInv[nn];
        h2s[nn*H2STR + k] = __uint_as_float(f2tf32(eluf(v*sA2[k] + sC2[k])));
    }
    __syncthreads();

    const uint32_t* h2u = (const uint32_t*)h2s;
    int w = t >> 5, l = t & 31;
    int g = l >> 2, c = l & 3;
    int mt = w & 1, nh = w >> 1;   // nh in 0..3: 64-col group
    int r0 = mt*16 + g;

    float acc[8][4];
    #pragma unroll
    for (int nt = 0; nt < 8; nt++) { acc[nt][0]=0; acc[nt][1]=0; acc[nt][2]=0; acc[nt][3]=0; }

    const uint32_t* ap = h2u + r0*H2STR + c;
    const uint32_t* wp = &g_WihT[c*256 + nh*64 + g];
    #pragma unroll
    for (int ks = 0; ks < 8; ks++) {
        const int kb = ks*8;
        uint32_t a[4];
        a[0] = ap[kb];
        a[1] = ap[kb + 8*H2STR];
        a[2] = ap[kb + 4];
        a[3] = ap[kb + 8*H2STR + 4];
        #pragma unroll
        for (int nt = 0; nt < 8; nt++) {
            uint32_t b[2];
            b[0] = __ldg(&wp[kb*256 + nt*8]);
            b[1] = __ldg(&wp[(kb + 4)*256 + nt*8]);
            mma_tf32(acc[nt], a, b);
        }
    }

    int n0 = nbase + r0, n1 = n0 + 8;
    int d0 = (ntime[n0]*G_GRAPHS + batch[n0])*C1;
    int d1 = (ntime[n1]*G_GRAPHS + batch[n1])*C1;
    #pragma unroll
    for (int nt = 0; nt < 8; nt++) {
        int col = nh*64 + nt*8 + 2*c;
        float bx = sBias[col], by = sBias[col+1];
        *(float2*)&g_xgates[d0 + col] = make_float2(acc[nt][0] + bx, acc[nt][1] + by);
        *(float2*)&g_xgates[d1 + col] = make_float2(acc[nt][2] + bx, acc[nt][3] + by);
    }
}

// LSTM: 1 graph/block (512 blocks), Whh row in regs, xgates prefetch, fused FC.
__global__ void __launch_bounds__(256) k_lstm(
        const float* __restrict__ Whh, const float* __restrict__ Wfc,
        const float* __restrict__ bfc, float* __restrict__ out) {
    __shared__ float hhs[64];
    __shared__ float gates[C1];
    int t = threadIdx.x;
    int g = blockIdx.x;

    unsigned long long w2[32];
    const float4* wrow = (const float4*)(Whh + t*64);
    #pragma unroll
    for (int i = 0; i < 16; i++) {
        float4 w = wrow[i];
        w2[2*i]   = pk(w.x, w.y);
        w2[2*i+1] = pk(w.z, w.w);
    }
    if (t < 64) hhs[t] = 0.f;
    float c = 0.f;
    float xg_cur = g_xgates[g*C1 + t];
    __syncthreads();

    for (int step = 0; step < T_STEPS; step++) {
        float xg_next = 0.f;
        if (step + 1 < T_STEPS) xg_next = g_xgates[((step+1)*G_GRAPHS + g)*C1 + t];
        unsigned long long aA = 0ull, aB = 0ull;
        #pragma unroll
        for (int k2 = 0; k2 < 16; k2++) {
            ulonglong2 hv = *(const ulonglong2*)&hhs[k2*4];
            ffma2(aA, hv.x, w2[2*k2]);
            ffma2(aB, hv.y, w2[2*k2+1]);
        }
        float2 a = unpk(aA), b = unpk(aB);
        gates[t] = xg_cur + a.x + a.y + b.x + b.y;
        __syncthreads();
        if (t < 64) {
            float ig = gates[t],       fg = gates[64 + t];
            float gg = gates[128 + t], og = gates[192 + t];
            c = sigf(fg)*c + sigf(ig)*tanhf(gg);
            hhs[t] = sigf(og)*tanhf(c);
        }
        __syncthreads();
        xg_cur = xg_next;
    }
    if (t < OUT_DIM) {
        float acc = bfc[t];
        #pragma unroll 8
        for (int k = 0; k < 64; k++) acc += hhs[k] * Wfc[k*OUT_DIM + t];
        out[g*OUT_DIM + t] = acc;
    }
}

// ---------------- launch ----------------
static const int SMEM_P2 = (2048 + P2N*H1STR + 64 + 64 + 128 + 128) * 4;   // 43008 B
static const int SMEM_XG = (XGN*H2STR + 256 + 64 + 64 + 32) * 4;           // 10368 B

extern "C" void kernel_launch(void* const* d_in, const int* in_sizes, int n_in,
                              void* d_out, int out_size) {
    const float* x    = (const float*)d_in[0];
    const int*   ei   = (const int*)  d_in[1];
    const int*   batch= (const int*)  d_in[2];
    const int*   ntime= (const int*)  d_in[3];
    const float* W1   = (const float*)d_in[4];
    const float* as1  = (const float*)d_in[5];
    const float* ad1  = (const float*)d_in[6];
    const float* b1   = (const float*)d_in[7];
    const float* g1   = (const float*)d_in[8];
    const float* be1  = (const float*)d_in[9];
    const float* W2   = (const float*)d_in[10];
    const float* as2  = (const float*)d_in[11];
    const float* ad2  = (const float*)d_in[12];
    const float* b2   = (const float*)d_in[13];
    const float* g2   = (const float*)d_in[14];
    const float* be2  = (const float*)d_in[15];
    const float* Wih  = (const float*)d_in[16];
    const float* Whh  = (const float*)d_in[17];
    const float* bih  = (const float*)d_in[18];
    const float* bhh  = (const float*)d_in[19];
    const float* Wfc  = (const float*)d_in[20];
    const float* bfc  = (const float*)d_in[21];
    float* out = (float*)d_out;

    cudaFuncSetAttribute(k_proj2f,  cudaFuncAttributeMaxDynamicSharedMemorySize, SMEM_P2);
    cudaFuncSetAttribute(k_xgates2, cudaFuncAttributeMaxDynamicSharedMemorySize, SMEM_XG);

    void* p_zbuf;
    cudaGetSymbolAddress(&p_zbuf, g_zbuf);
    cudaMemsetAsync(p_zbuf, 0, sizeof(float)*ZBUF_FLOATS);

    k_prep2  <<<N_NODES/256, 256>>>(W1, as1, ad1, W2, Wih, x);            // launch 1
    k_esum1  <<<(EHALF + 255)/256, 256>>>(ei);                            // launch 2
    k_proj2f <<<N_NODES/P2N, 256, SMEM_P2>>>(W1, b1, g1, be1, as2, ad2);  // launch 3
    k_esum2  <<<(EHALF*8 + 255)/256, 256>>>(ei);                          // launch 4 (profiled)
    k_xgates2<<<N_NODES/XGN, 256, SMEM_XG>>>(bih, bhh, b2, g2, be2, batch, ntime);
    k_lstm   <<<G_GRAPHS, 256>>>(Whh, Wfc, bfc, out);
}